// round 16
// baseline (speedup 1.0000x reference)
#include <cuda_runtime.h>
#include <cuda_bf16.h>
#include <cstdint>

#define BB 4
#define TT 4096
#define CC 1024
#define HS 64
#define SCALE 0.03125f   // CC^-0.5 = 1/32 (reference scales by n_embd, not head_size)

// Scratch for q,k,v projections: [B,T,HS] fp32 each
__device__ float g_q[BB * TT * HS];
__device__ float g_k[BB * TT * HS];
__device__ float g_v[BB * TT * HS];

// ===========================================================================
// mma.sync / ldmatrix helpers (base PTX, legal on plain sm_100)
// ===========================================================================
__device__ __forceinline__ uint32_t smem_u32(const void* p) {
    uint32_t a;
    asm("{ .reg .u64 t; cvta.to.shared.u64 t, %1; cvt.u32.u64 %0, t; }"
        : "=r"(a) : "l"(p));
    return a;
}

__device__ __forceinline__ void ldsm4(uint32_t* r, uint32_t a) {
    asm volatile("ldmatrix.sync.aligned.m8n8.x4.shared.b16 {%0,%1,%2,%3}, [%4];"
        : "=r"(r[0]), "=r"(r[1]), "=r"(r[2]), "=r"(r[3]) : "r"(a));
}
__device__ __forceinline__ void ldsm4t(uint32_t* r, uint32_t a) {
    asm volatile("ldmatrix.sync.aligned.m8n8.x4.trans.shared.b16 {%0,%1,%2,%3}, [%4];"
        : "=r"(r[0]), "=r"(r[1]), "=r"(r[2]), "=r"(r[3]) : "r"(a));
}
// D += A*B, m16n8k16 bf16, fp32 accum (in-place)
__device__ __forceinline__ void mma16816(float* d, const uint32_t* a, const uint32_t* b) {
    asm volatile(
        "mma.sync.aligned.m16n8k16.row.col.f32.bf16.bf16.f32 "
        "{%0,%1,%2,%3}, {%4,%5,%6,%7}, {%8,%9}, {%0,%1,%2,%3};"
        : "+f"(d[0]), "+f"(d[1]), "+f"(d[2]), "+f"(d[3])
        : "r"(a[0]), "r"(a[1]), "r"(a[2]), "r"(a[3]), "r"(b[0]), "r"(b[1]));
}

__device__ __forceinline__ uint32_t pk2(float x, float y) {
    __nv_bfloat162 t = __floats2bfloat162_rn(x, y);
    return *reinterpret_cast<uint32_t*>(&t);
}
__device__ __forceinline__ float bhi(float x) {
    return __bfloat162float(__float2bfloat16_rn(x));
}

// All bf16 tiles: row-major, 64 cols = 128B rows, 16B chunks swizzled chunk^=(row&7)
// A-operand x4 (non-trans)
__device__ __forceinline__ uint32_t a_addr(uint32_t base, int lane, int mbase, int cbase) {
    int t = lane >> 3, r = lane & 7;
    int row = mbase + ((t & 1) << 3) + r;
    int chunk = cbase + (t >> 1);
    return base + row * 128 + (((chunk ^ (row & 7))) << 4);
}
// B from K-style storage [n][k] (non-trans): 2 n-tiles x k16
__device__ __forceinline__ uint32_t bk_addr(uint32_t base, int lane, int nbase, int cbase) {
    int t = lane >> 3, r = lane & 7;
    int row = nbase + ((t >> 1) << 3) + r;
    int chunk = cbase + (t & 1);
    return base + row * 128 + (((chunk ^ (row & 7))) << 4);
}
// B from V-style storage [k][n] (.trans): k32 x one 8-col chunk
__device__ __forceinline__ uint32_t bv_addr(uint32_t base, int lane, int krow0, int chunk) {
    int t = lane >> 3, r = lane & 7;
    int row = krow0 + ((t >> 1) << 4) + ((t & 1) << 3) + r;
    return base + row * 128 + (((chunk ^ (row & 7))) << 4);
}
// B from W-style storage [k][n] (.trans): fixed k16, 2 n-tiles
__device__ __forceinline__ uint32_t bw_addr(uint32_t base, int lane, int krow0, int ntchunk0) {
    int t = lane >> 3, r = lane & 7;
    int row = krow0 + ((t & 1) << 3) + r;
    int chunk = ntchunk0 + (t >> 1);
    return base + row * 128 + (((chunk ^ (row & 7))) << 4);
}

// split fp32 float4 -> hi/lo bf16x4 (8B each) and store at swizzled offset
__device__ __forceinline__ void split_store(char* hi_b, char* lo_b, int row, int q4, float4 v) {
    uint32_t off = (uint32_t)(row * 128 + ((((q4 >> 1) ^ (row & 7))) << 4) + ((q4 & 1) << 3));
    uint2 h, l;
    h.x = pk2(v.x, v.y); h.y = pk2(v.z, v.w);
    l.x = pk2(v.x - bhi(v.x), v.y - bhi(v.y));
    l.y = pk2(v.z - bhi(v.z), v.w - bhi(v.w));
    *(uint2*)(hi_b + off) = h;
    *(uint2*)(lo_b + off) = l;
}

// ===========================================================================
// Kernel 1: QKV projection, mma.sync bf16 3-product.  (byte-exact R14 PASS,
// measured ~59us)
// ===========================================================================
#define QKV_STAGE 81920
#define QKV_SMEM_BYTES (2 * QKV_STAGE + 768)

__global__ __launch_bounds__(256) void qkv_mma(
    const float* __restrict__ x,
    const float* __restrict__ Wq, const float* __restrict__ bq,
    const float* __restrict__ Wk, const float* __restrict__ bk,
    const float* __restrict__ Wv, const float* __restrict__ bv)
{
    extern __shared__ char sm[];
    float* bias_s = (float*)(sm + 2 * QKV_STAGE);

    const uint32_t sm_u = smem_u32(sm);
    const int tid  = threadIdx.x;
    const int wid  = tid >> 5;
    const int lane = tid & 31;
    const int tg   = lane & 3;
    const int g    = lane >> 2;
    const int m0   = blockIdx.x * 128;
    const int wm   = 16 * wid;
    const int xrow = tid >> 4, xq4 = tid & 15;

    if (tid < 192) {
        const float* bp = (tid < 64) ? bq : ((tid < 128) ? bk : bv);
        bias_s[tid] = bp[tid & 63];
    }

    float4 xr[8];
    float4 wr[3][4];
    #pragma unroll
    for (int i = 0; i < 8; i++)
        xr[i] = *(const float4*)(x + (size_t)(m0 + xrow + i * 16) * CC + xq4 * 4);
    #pragma unroll
    for (int ws = 0; ws < 3; ws++) {
        const float* Wp = (ws == 0) ? Wq : ((ws == 1) ? Wk : Wv);
        #pragma unroll
        for (int i = 0; i < 4; i++)
            wr[ws][i] = *(const float4*)(Wp + (size_t)(xrow + i * 16) * HS + xq4 * 4);
    }

    float acc[24][4];
    #pragma unroll
    for (int i = 0; i < 24; i++)
        #pragma unroll
        for (int c = 0; c < 4; c++) acc[i][c] = 0.f;

    for (int kb = 0; kb < 16; kb++) {
        const int st = kb & 1;
        char* base = sm + st * QKV_STAGE;
        const uint32_t base_u = sm_u + st * QKV_STAGE;

        #pragma unroll
        for (int i = 0; i < 8; i++)
            split_store(base, base + 16384, xrow + i * 16, xq4, xr[i]);
        #pragma unroll
        for (int ws = 0; ws < 3; ws++)
            #pragma unroll
            for (int i = 0; i < 4; i++)
                split_store(base + 32768 + ws * 8192, base + 57344 + ws * 8192,
                            xrow + i * 16, xq4, wr[ws][i]);
        __syncthreads();

        if (kb < 15) {
            const int k1 = (kb + 1) * 64;
            #pragma unroll
            for (int i = 0; i < 8; i++)
                xr[i] = *(const float4*)(x + (size_t)(m0 + xrow + i * 16) * CC + k1 + xq4 * 4);
            #pragma unroll
            for (int ws = 0; ws < 3; ws++) {
                const float* Wp = (ws == 0) ? Wq : ((ws == 1) ? Wk : Wv);
                #pragma unroll
                for (int i = 0; i < 4; i++)
                    wr[ws][i] = *(const float4*)(Wp + (size_t)(k1 + xrow + i * 16) * HS + xq4 * 4);
            }
        }

        const uint32_t xhi_u = base_u, xlo_u = base_u + 16384;
        const uint32_t whi_u = base_u + 32768, wlo_u = base_u + 57344;
        #pragma unroll
        for (int kc = 0; kc < 4; kc++) {
            uint32_t ah[4], al4[4];
            ldsm4(ah,  a_addr(xhi_u, lane, wm, kc * 2));
            ldsm4(al4, a_addr(xlo_u, lane, wm, kc * 2));
            #pragma unroll
            for (int p = 0; p < 12; p++) {
                int gnt  = 2 * p;
                int wsel = gnt >> 3;
                int lnt  = gnt & 7;
                uint32_t bh[4], bl[4];
                ldsm4t(bh, bw_addr(whi_u + wsel * 8192, lane, kc * 16, lnt));
                ldsm4t(bl, bw_addr(wlo_u + wsel * 8192, lane, kc * 16, lnt));
                #pragma unroll
                for (int i = 0; i < 2; i++) {
                    int ln = gnt + i;
                    mma16816(acc[ln], ah,  &bh[2 * i]);
                    mma16816(acc[ln], ah,  &bl[2 * i]);
                    mma16816(acc[ln], al4, &bh[2 * i]);
                }
            }
        }
    }

    #pragma unroll
    for (int nt = 0; nt < 24; nt++) {
        int wsel = nt >> 3;
        int col  = (nt & 7) * 8 + 2 * tg;
        float* op = (wsel == 0) ? g_q : ((wsel == 1) ? g_k : g_v);
        float b0 = bias_s[wsel * 64 + col];
        float b1 = bias_s[wsel * 64 + col + 1];
        float2 o0 = make_float2(acc[nt][0] + b0, acc[nt][1] + b1);
        float2 o1 = make_float2(acc[nt][2] + b0, acc[nt][3] + b1);
        *(float2*)(op + (size_t)(m0 + wm + g)     * HS + col) = o0;
        *(float2*)(op + (size_t)(m0 + wm + g + 8) * HS + col) = o1;
    }
}

// ===========================================================================
// Kernel 2: flash attention, ALL-CONSUMER (8 warps x 16 rows x 32 key-cols).
// Warp w: rows 16*(w&3), key-col half 32*(w>>2). Partner = w^4 (same rows).
// Row max exchanged via smem + pairwise named barrier; each warp keeps own
// partial l and partial O (full 64 output cols) under the shared alpha chain;
// partners merged once per half in the epilogue.
// K/V double buffer; next tile staged in registers by all warps (LDG issued
// before S-mma), stored after PV, 1 rotation __syncthreads per tile.
// ===========================================================================
// smem: Qhi 0, Qlo 8192; buf s at 16384+s*32768 (Khi/Klo/Vhi/Vlo 8K each);
// pmax 81920 (8 warps x 16 rows), lrx 82432 (4 x 16). merge reuses buf0.
#define ATTN_SMEM_BYTES (16384 + 2 * 32768 + 1024)

__global__ __launch_bounds__(256) void attn_mma(float* __restrict__ out)
{
    extern __shared__ char sm[];
    const uint32_t sm_u = smem_u32(sm);

    const int tid  = threadIdx.x;
    const int wid  = tid >> 5;
    const int lane = tid & 31;
    const int g    = lane >> 2;
    const int tg   = lane & 3;
    const int wr4  = wid & 3;           // row group
    const int cw   = wid >> 2;          // key-col half (0/1)
    const int wm   = 16 * wr4;
    const int partner = wid ^ 4;
    const int xrow = tid >> 4, xq4 = tid & 15;

    float* pmax = (float*)(sm + 81920);  // [8][16]
    float* lrx  = (float*)(sm + 82432);  // [4][16]

    const int b    = blockIdx.y;
    const int pair = blockIdx.x;         // 0..31

    const float* qb = g_q + (size_t)b * TT * HS;
    const float* kb = g_k + (size_t)b * TT * HS;
    const float* vb = g_v + (size_t)b * TT * HS;
    float*       ob = out + (size_t)b * TT * HS;

    for (int half = 0; half < 2; half++) {
        const int qtile = half ? (TT / 64 - 1 - pair) : pair;
        const int m0 = qtile * 64;

        __syncthreads();   // previous half's smem reads done

        // ---- load Q tile (all threads, 4 float4 each) ----
        #pragma unroll
        for (int i = 0; i < 4; i++) {
            float4 v = *(const float4*)(qb + (size_t)(m0 + xrow + i * 16) * HS + xq4 * 4);
            split_store(sm, sm + 8192, xrow + i * 16, xq4, v);
        }
        // ---- prefill buf0 with K/V tile 0 ----
        {
            char* b0 = sm + 16384;
            #pragma unroll
            for (int i = 0; i < 4; i++) {
                float4 kv4 = *(const float4*)(kb + (size_t)(xrow + i * 16) * HS + xq4 * 4);
                float4 vv4 = *(const float4*)(vb + (size_t)(xrow + i * 16) * HS + xq4 * 4);
                split_store(b0,         b0 + 8192,  xrow + i * 16, xq4, kv4);
                split_store(b0 + 16384, b0 + 24576, xrow + i * 16, xq4, vv4);
            }
        }
        __syncthreads();

        // persistent Q fragments
        uint32_t qh[4][4], ql[4][4];
        #pragma unroll
        for (int kc = 0; kc < 4; kc++) {
            ldsm4(qh[kc], a_addr(sm_u,        lane, wm, kc * 2));
            ldsm4(ql[kc], a_addr(sm_u + 8192, lane, wm, kc * 2));
        }

        float o[8][4];
        float mr0 = -1e30f, mr1 = -1e30f, lr0 = 0.f, lr1 = 0.f;
        #pragma unroll
        for (int ct = 0; ct < 8; ct++)
            #pragma unroll
            for (int c = 0; c < 4; c++) o[ct][c] = 0.f;

        for (int j = 0; j <= qtile; j++) {
            const int s = j & 1;
            const uint32_t kbu = sm_u + 16384 + s * 32768;

            // ---- stage next tile's K/V (LDG early; latency hidden) ----
            float4 stg[8];
            const bool havenext = (j < qtile);
            if (havenext) {
                const int n1 = (j + 1) * 64;
                #pragma unroll
                for (int i = 0; i < 4; i++) {
                    stg[i]     = *(const float4*)(kb + (size_t)(n1 + xrow + i * 16) * HS + xq4 * 4);
                    stg[4 + i] = *(const float4*)(vb + (size_t)(n1 + xrow + i * 16) * HS + xq4 * 4);
                }
            }

            // ---- S = Q K^T : 16 rows x 32 cols (this warp's half) ----
            float sa[4][4];
            #pragma unroll
            for (int nt = 0; nt < 4; nt++)
                #pragma unroll
                for (int c = 0; c < 4; c++) sa[nt][c] = 0.f;

            #pragma unroll
            for (int kc = 0; kc < 4; kc++) {
                #pragma unroll
                for (int ntp = 0; ntp < 2; ntp++) {
                    int nbase = 32 * cw + 16 * ntp;
                    uint32_t kh[4], kl4[4];
                    ldsm4(kh,  bk_addr(kbu,        lane, nbase, kc * 2));
                    ldsm4(kl4, bk_addr(kbu + 8192, lane, nbase, kc * 2));
                    #pragma unroll
                    for (int i = 0; i < 2; i++) {
                        int nt = 2 * ntp + i;
                        mma16816(sa[nt], qh[kc], &kh[2 * i]);
                        mma16816(sa[nt], qh[kc], &kl4[2 * i]);
                        mma16816(sa[nt], ql[kc], &kh[2 * i]);
                    }
                }
            }

            // ---- scale + causal mask ----
            if (j == qtile) {
                #pragma unroll
                for (int nt = 0; nt < 4; nt++) {
                    int c0 = 32 * cw + nt * 8 + 2 * tg;
                    sa[nt][0] = (c0     <= wm + g)     ? sa[nt][0] * SCALE : -1e30f;
                    sa[nt][1] = (c0 + 1 <= wm + g)     ? sa[nt][1] * SCALE : -1e30f;
                    sa[nt][2] = (c0     <= wm + g + 8) ? sa[nt][2] * SCALE : -1e30f;
                    sa[nt][3] = (c0 + 1 <= wm + g + 8) ? sa[nt][3] * SCALE : -1e30f;
                }
            } else {
                #pragma unroll
                for (int nt = 0; nt < 4; nt++)
                    #pragma unroll
                    for (int c = 0; c < 4; c++) sa[nt][c] *= SCALE;
            }

            // ---- partial row max over this warp's 32 cols ----
            float tm0 = -1e30f, tm1 = -1e30f;
            #pragma unroll
            for (int nt = 0; nt < 4; nt++) {
                tm0 = fmaxf(tm0, fmaxf(sa[nt][0], sa[nt][1]));
                tm1 = fmaxf(tm1, fmaxf(sa[nt][2], sa[nt][3]));
            }
            tm0 = fmaxf(tm0, __shfl_xor_sync(0xffffffffu, tm0, 1));
            tm0 = fmaxf(tm0, __shfl_xor_sync(0xffffffffu, tm0, 2));
            tm1 = fmaxf(tm1, __shfl_xor_sync(0xffffffffu, tm1, 1));
            tm1 = fmaxf(tm1, __shfl_xor_sync(0xffffffffu, tm1, 2));
            if (tg == 0) {
                pmax[wid * 16 + g]     = tm0;
                pmax[wid * 16 + 8 + g] = tm1;
            }
            // pairwise named barrier: partner warps (wid, wid^4), 64 threads
            asm volatile("bar.sync %0, %1;" :: "r"(1 + wr4), "r"(64) : "memory");
            float pm0 = pmax[partner * 16 + g];
            float pm1 = pmax[partner * 16 + 8 + g];

            float mn0 = fmaxf(mr0, fmaxf(tm0, pm0));
            float mn1 = fmaxf(mr1, fmaxf(tm1, pm1));
            float al0 = __expf(mr0 - mn0), al1 = __expf(mr1 - mn1);
            mr0 = mn0; mr1 = mn1;
            float rs0 = 0.f, rs1 = 0.f;
            #pragma unroll
            for (int nt = 0; nt < 4; nt++) {
                sa[nt][0] = __expf(sa[nt][0] - mn0);
                sa[nt][1] = __expf(sa[nt][1] - mn0);
                sa[nt][2] = __expf(sa[nt][2] - mn1);
                sa[nt][3] = __expf(sa[nt][3] - mn1);
                rs0 += sa[nt][0] + sa[nt][1];
                rs1 += sa[nt][2] + sa[nt][3];
            }
            rs0 += __shfl_xor_sync(0xffffffffu, rs0, 1);
            rs0 += __shfl_xor_sync(0xffffffffu, rs0, 2);
            rs1 += __shfl_xor_sync(0xffffffffu, rs1, 1);
            rs1 += __shfl_xor_sync(0xffffffffu, rs1, 2);
            lr0 = lr0 * al0 + rs0;       // own partial only; partner merged at end
            lr1 = lr1 * al1 + rs1;
            #pragma unroll
            for (int ct = 0; ct < 8; ct++) {
                o[ct][0] *= al0; o[ct][1] *= al0;
                o[ct][2] *= al1; o[ct][3] *= al1;
            }

            // ---- O += P_w * V[this warp's 32 keys] (partial O, full 64 cols) ----
            {
                const uint32_t Vhi_u = kbu + 16384, Vlo_u = kbu + 24576;
                uint32_t ph[2][4], pl[2][4];
                #pragma unroll
                for (int i = 0; i < 2; i++) {
                    int t0 = 2 * i;
                    ph[i][0] = pk2(sa[t0][0], sa[t0][1]);
                    ph[i][1] = pk2(sa[t0][2], sa[t0][3]);
                    ph[i][2] = pk2(sa[t0 + 1][0], sa[t0 + 1][1]);
                    ph[i][3] = pk2(sa[t0 + 1][2], sa[t0 + 1][3]);
                    pl[i][0] = pk2(sa[t0][0] - bhi(sa[t0][0]), sa[t0][1] - bhi(sa[t0][1]));
                    pl[i][1] = pk2(sa[t0][2] - bhi(sa[t0][2]), sa[t0][3] - bhi(sa[t0][3]));
                    pl[i][2] = pk2(sa[t0 + 1][0] - bhi(sa[t0 + 1][0]), sa[t0 + 1][1] - bhi(sa[t0 + 1][1]));
                    pl[i][3] = pk2(sa[t0 + 1][2] - bhi(sa[t0 + 1][2]), sa[t0 + 1][3] - bhi(sa[t0 + 1][3]));
                }
                #pragma unroll
                for (int ct = 0; ct < 8; ct++) {
                    uint32_t vh[4], vl[4];
                    ldsm4t(vh, bv_addr(Vhi_u, lane, 32 * cw, ct));
                    ldsm4t(vl, bv_addr(Vlo_u, lane, 32 * cw, ct));
                    #pragma unroll
                    for (int i = 0; i < 2; i++) {
                        mma16816(o[ct], ph[i], &vh[2 * i]);
                        mma16816(o[ct], ph[i], &vl[2 * i]);
                        mma16816(o[ct], pl[i], &vh[2 * i]);
                    }
                }
            }

            // ---- store staged K/V into the other buffer ----
            if (havenext) {
                char* nb = sm + 16384 + (s ^ 1) * 32768;
                #pragma unroll
                for (int i = 0; i < 4; i++) {
                    split_store(nb,         nb + 8192,  xrow + i * 16, xq4, stg[i]);
                    split_store(nb + 16384, nb + 24576, xrow + i * 16, xq4, stg[4 + i]);
                }
            }
            __syncthreads();
        }

        // ---- epilogue: merge partner partial O and l, then store ----
        float* mrg = (float*)(sm + 16384);   // 4 regions of 16x64 floats (reuses buf0)
        if (cw == 1) {
            float* reg = mrg + wr4 * (16 * 64);
            #pragma unroll
            for (int ct = 0; ct < 8; ct++) {
                *(float2*)&reg[g * 64 + ct * 8 + 2 * tg]       = make_float2(o[ct][0], o[ct][1]);
                *(float2*)&reg[(g + 8) * 64 + ct * 8 + 2 * tg] = make_float2(o[ct][2], o[ct][3]);
            }
            if (tg == 0) {
                lrx[wr4 * 16 + g]     = lr0;
                lrx[wr4 * 16 + 8 + g] = lr1;
            }
        }
        __syncthreads();
        if (cw == 0) {
            float* reg = mrg + wr4 * (16 * 64);
            float lt0 = lr0 + lrx[wr4 * 16 + g];
            float lt1 = lr1 + lrx[wr4 * 16 + 8 + g];
            float inv0 = 1.0f / lt0, inv1 = 1.0f / lt1;
            #pragma unroll
            for (int ct = 0; ct < 8; ct++) {
                int col = ct * 8 + 2 * tg;
                float2 p0 = *(float2*)&reg[g * 64 + col];
                float2 p1 = *(float2*)&reg[(g + 8) * 64 + col];
                float2 o0 = make_float2((o[ct][0] + p0.x) * inv0, (o[ct][1] + p0.y) * inv0);
                float2 o1 = make_float2((o[ct][2] + p1.x) * inv1, (o[ct][3] + p1.y) * inv1);
                *(float2*)(ob + (size_t)(m0 + wm + g)     * HS + col) = o0;
                *(float2*)(ob + (size_t)(m0 + wm + g + 8) * HS + col) = o1;
            }
        }
        // top-of-half __syncthreads orders merge-buffer reuse
    }
}

// ---------------------------------------------------------------------------
extern "C" void kernel_launch(void* const* d_in, const int* in_sizes, int n_in,
                              void* d_out, int out_size)
{
    const float* x  = (const float*)d_in[0];
    const float* Wq = (const float*)d_in[1];
    const float* bq = (const float*)d_in[2];
    const float* Wk = (const float*)d_in[3];
    const float* bk = (const float*)d_in[4];
    const float* Wv = (const float*)d_in[5];
    const float* bv = (const float*)d_in[6];
    float* out = (float*)d_out;

    (void)cudaFuncSetAttribute(qkv_mma,
                               cudaFuncAttributeMaxDynamicSharedMemorySize,
                               QKV_SMEM_BYTES);
    (void)cudaFuncSetAttribute(attn_mma,
                               cudaFuncAttributeMaxDynamicSharedMemorySize,
                               ATTN_SMEM_BYTES);

    qkv_mma<<<(BB * TT) / 128, 256, QKV_SMEM_BYTES>>>(x, Wq, bq, Wk, bk, Wv, bv);
    attn_mma<<<dim3(TT / 64 / 2, BB), 256, ATTN_SMEM_BYTES>>>(out);
}